// round 9
// baseline (speedup 1.0000x reference)
#include <cuda_runtime.h>
#include <cstdint>

// Problem constants
#define B_   4
#define C_   128
#define H_   192
#define W_   192
#define HW_  (H_*W_)
#define K_   9
#define PAD  4
#define NOFF 81

// Tiling
#define TH   8
#define TW   16
#define PXT  4                 // pixels per thread
#define NTHREADS 288           // 4 wg * 9 io * 8 hr
#define CH   8
#define NSTAGE 16
#define YROWS 16               // TH + 2*PAD
#define YPITCH 48              // odd-row-delta*48 ≡ 16 mod 32 -> conflict-free LDS phases
#define XPITCH 16
#define XSZ  (CH*TH*XPITCH)    // 1024 floats
#define YSZ  (CH*YROWS*YPITCH) // 6144 floats
#define BUFSZ (XSZ + YSZ)      // 7168 floats
#define SMEM_BYTES (2*BUFSZ*4) // 57344 bytes

typedef unsigned long long u64;

__device__ __forceinline__ u64 pack2(float lo, float hi) {
    u64 r;
    asm("mov.b64 %0, {%1, %2};" : "=l"(r) : "f"(lo), "f"(hi));
    return r;
}
__device__ __forceinline__ u64 ffma2u(u64 a, u64 b, u64 c) {
    u64 d;
    asm("fma.rn.f32x2 %0, %1, %2, %3;" : "=l"(d) : "l"(a), "l"(b), "l"(c));
    return d;
}
__device__ __forceinline__ float2 unpack2(u64 v) {
    float2 r;
    asm("mov.b64 {%0, %1}, %2;" : "=f"(r.x), "=f"(r.y) : "l"(v));
    return r;
}

__device__ __forceinline__ void cp16(uint32_t dst, const void* src, int srcsize) {
    asm volatile("cp.async.cg.shared.global [%0], [%1], 16, %2;"
                 :: "r"(dst), "l"(src), "r"(srcsize));
}
__device__ __forceinline__ void cp_commit() {
    asm volatile("cp.async.commit_group;");
}
template <int N>
__device__ __forceinline__ void cp_wait() {
    asm volatile("cp.async.wait_group %0;" :: "n"(N));
}

__global__ void __launch_bounds__(NTHREADS, 3)
corr_kernel(const float* __restrict__ x,
            const float* __restrict__ y,
            float* __restrict__ out) {
    extern __shared__ float sm[];

    const int tid = threadIdx.x;
    const int wg  = tid & 3;          // 4 pixel groups of 4
    const int io  = (tid >> 2) % 9;
    const int hr  = tid / 36;

    const int b  = blockIdx.z;
    const int h0 = blockIdx.y * TH;
    const int w0 = blockIdx.x * TW;

    const float* xb = x + (size_t)b * C_ * HW_;
    const float* yb = y + (size_t)b * C_ * HW_;

    const uint32_t sm_base = (uint32_t)__cvta_generic_to_shared(sm);

    // ---- stage prefetch: no div/mod, per-thread row ownership for y ----
    auto prefetch = [&](int s, int buf) {
        const int c0 = s * CH;
        const uint32_t base = sm_base + (uint32_t)(buf * BUFSZ) * 4u;

        // x tile: 256 threads, 1 float4 each (always in-bounds)
        if (tid < 256) {
            int c  = tid >> 5;
            int r  = (tid >> 2) & 7;
            int c4 = tid & 3;
            const float* src = xb + (size_t)(c0 + c) * HW_ + (h0 + r) * W_ + w0 + c4 * 4;
            cp16(base + (uint32_t)((c * TH + r) * XPITCH + c4 * 4) * 4u, src, 16);
        }
        // y halo: 128 threads own one smem row (c, r); 6 float4, origin (h0-4, w0-4)
        if (tid < 128) {
            int c  = tid >> 4;
            int r  = tid & 15;
            int gh = h0 + r - PAD;
            bool rowok = (unsigned)gh < (unsigned)H_;
            const float* srow = yb + (size_t)(c0 + c) * HW_ + gh * W_ + (w0 - 4);
            uint32_t dst = base + (uint32_t)(XSZ + (c * YROWS + r) * YPITCH) * 4u;
#pragma unroll
            for (int q = 0; q < 6; q++) {
                int gw = w0 - 4 + q * 4;
                bool ok = rowok && (gw >= 0) && (gw <= W_ - 4);
                cp16(dst + (uint32_t)q * 16u, ok ? (srow + q * 4) : (const float*)yb,
                     ok ? 16 : 0);
            }
        }
        cp_commit();
    };

    // accumulators: acc[j][q], pixel pair (2q, 2q+1); 18 u64 = 36 regs
    u64 acc[K_][2];
#pragma unroll
    for (int j = 0; j < K_; j++) { acc[j][0] = 0ull; acc[j][1] = 0ull; }

    prefetch(0, 0);

    for (int s = 0; s < NSTAGE; s++) {
        cp_wait<0>();              // exactly one pending group = stage s -> wait it out
        __syncthreads();           // (a) everyone's stage-s data visible
                                   // (b) all compute(s-1) done -> buf (s+1)&1 free
        if (s + 1 < NSTAGE) prefetch(s + 1, (s + 1) & 1);   // overlaps compute(s)

        const int buf = s & 1;
        const float* xp   = sm + buf * BUFSZ + hr * XPITCH + wg * PXT;
        const float* yrow = sm + buf * BUFSZ + XSZ + (hr + io) * YPITCH + wg * PXT;

#pragma unroll
        for (int c = 0; c < CH; c++) {
            float4 xa = *(const float4*)xp;
            u64 xe0 = pack2(xa.x, xa.y);   // adjacent lanes of float4 -> coalescible
            u64 xe1 = pack2(xa.z, xa.w);

            float4 y0 = *(const float4*)(yrow);
            float4 y1 = *(const float4*)(yrow + 4);
            float4 y2 = *(const float4*)(yrow + 8);
            float yv[12] = {y0.x, y0.y, y0.z, y0.w,
                            y1.x, y1.y, y1.z, y1.w,
                            y2.x, y2.y, y2.z, y2.w};

            // even-aligned y pairs (coalescible packs)
            u64 ye[6];
#pragma unroll
            for (int t = 0; t < 6; t++) ye[t] = pack2(yv[2 * t], yv[2 * t + 1]);
            // odd-aligned y pairs (genuine movs, 5)
            u64 yo[5];
#pragma unroll
            for (int t = 0; t < 5; t++) yo[t] = pack2(yv[2 * t + 1], yv[2 * t + 2]);

            // even j = 2*je: pair index q + je
#pragma unroll
            for (int je = 0; je < 5; je++) {
                acc[2 * je][0] = ffma2u(xe0, ye[je],     acc[2 * je][0]);
                acc[2 * je][1] = ffma2u(xe1, ye[je + 1], acc[2 * je][1]);
            }
            // odd j = 2*jo+1: odd pair index q + jo
#pragma unroll
            for (int jo = 0; jo < 4; jo++) {
                acc[2 * jo + 1][0] = ffma2u(xe0, yo[jo],     acc[2 * jo + 1][0]);
                acc[2 * jo + 1][1] = ffma2u(xe1, yo[jo + 1], acc[2 * jo + 1][1]);
            }

            xp   += TH * XPITCH;
            yrow += YROWS * YPITCH;
        }
    }

    // ---- epilogue: 9 float4 stores ----
    const float inv_c = 1.0f / (float)C_;
    const int hrow = h0 + hr;
#pragma unroll
    for (int j = 0; j < K_; j++) {
        int o = io * K_ + j;
        float* op = out + (((size_t)b * NOFF + o) * H_ + hrow) * W_ + w0 + wg * PXT;
        float2 v0 = unpack2(acc[j][0]);
        float2 v1 = unpack2(acc[j][1]);
        *(float4*)op = make_float4(v0.x * inv_c, v0.y * inv_c,
                                   v1.x * inv_c, v1.y * inv_c);
    }
}

extern "C" void kernel_launch(void* const* d_in, const int* in_sizes, int n_in,
                              void* d_out, int out_size) {
    const float* x = (const float*)d_in[0];
    const float* y = (const float*)d_in[1];
    float* out = (float*)d_out;

    static bool attr_set = false;
    if (!attr_set) {
        cudaFuncSetAttribute(corr_kernel,
                             cudaFuncAttributeMaxDynamicSharedMemorySize,
                             SMEM_BYTES);
        attr_set = true;
    }

    dim3 grid(W_ / TW, H_ / TH, B_);   // 12 x 24 x 4 = 1152 blocks
    corr_kernel<<<grid, NTHREADS, SMEM_BYTES>>>(x, y, out);
}

// round 10
// speedup vs baseline: 1.1007x; 1.1007x over previous
#include <cuda_runtime.h>
#include <cstdint>

// Problem constants
#define B_   4
#define C_   128
#define H_   192
#define W_   192
#define HW_  (H_*W_)
#define K_   9
#define PAD  4
#define NOFF 81

// Tiling
#define TH   8
#define TW   16
#define PXT  4                 // pixels per thread
#define NTHREADS 288           // 4 wg * 9 io * 8 hr
#define CH   8
#define NSTAGE 16
#define YROWS 16               // TH + 2*PAD
#define YCHUNK 6               // stored y chunks/row: 24 floats, origin w0-4
#define YPITCH 48              // odd-row-delta*48 ≡ 16 mod 32 -> conflict-free LDS phases
#define XPITCH 16
#define XSZ  (CH*TH*XPITCH)    // 1024 floats
#define YSZ  (CH*YROWS*YPITCH) // 6144 floats
#define BUFSZ (XSZ + YSZ)      // 7168 floats
#define SMEM_BYTES (2*BUFSZ*4) // 57344 bytes

typedef unsigned long long u64;

__device__ __forceinline__ u64 pack2(float lo, float hi) {
    u64 r;
    asm("mov.b64 %0, {%1, %2};" : "=l"(r) : "f"(lo), "f"(hi));
    return r;
}
__device__ __forceinline__ u64 ffma2u(u64 a, u64 b, u64 c) {
    u64 d;
    asm("fma.rn.f32x2 %0, %1, %2, %3;" : "=l"(d) : "l"(a), "l"(b), "l"(c));
    return d;
}
__device__ __forceinline__ float2 unpack2(u64 v) {
    float2 r;
    asm("mov.b64 {%0, %1}, %2;" : "=f"(r.x), "=f"(r.y) : "l"(v));
    return r;
}

__device__ __forceinline__ void cp16(uint32_t dst, const void* src, int srcsize) {
    asm volatile("cp.async.cg.shared.global [%0], [%1], 16, %2;"
                 :: "r"(dst), "l"(src), "r"(srcsize));
}
__device__ __forceinline__ void cp_commit() {
    asm volatile("cp.async.commit_group;");
}
template <int N>
__device__ __forceinline__ void cp_wait() {
    asm volatile("cp.async.wait_group %0;" :: "n"(N));
}

__global__ void __launch_bounds__(NTHREADS, 3)
corr_kernel(const float* __restrict__ x,
            const float* __restrict__ y,
            float* __restrict__ out) {
    extern __shared__ float sm[];

    const int tid = threadIdx.x;
    const int wg  = tid & 3;          // 4 pixel groups of 4
    const int io  = (tid >> 2) % 9;
    const int hr  = tid / 36;

    const int b  = blockIdx.z;
    const int h0 = blockIdx.y * TH;
    const int w0 = blockIdx.x * TW;

    const float* xb = x + (size_t)b * C_ * HW_;
    const float* yb = y + (size_t)b * C_ * HW_;

    const uint32_t sm_base = (uint32_t)__cvta_generic_to_shared(sm);

    // ---- stage prefetch: R8 spread mapping (coalesced), trimmed y halo ----
    auto prefetch = [&](int s, int buf) {
        const int c0 = s * CH;
        const uint32_t xs_base = sm_base + (uint32_t)(buf * BUFSZ) * 4u;
        const uint32_t ys_base = xs_base + (uint32_t)XSZ * 4u;

        // x tile: CH*TH*4 = 256 float4, always in-bounds, one round
        if (tid < 256) {
            int c  = tid >> 5;          // 32 float4 per channel
            int r  = (tid >> 2) & 7;
            int c4 = tid & 3;
            const float* src = xb + (size_t)(c0 + c) * HW_ + (h0 + r) * W_ + w0 + c4 * 4;
            cp16(xs_base + (uint32_t)((c * TH + r) * XPITCH + c4 * 4) * 4u, src, 16);
        }
        // y halo tile: CH*16*6 = 768 float4, origin (h0-4, w0-4)
        // consecutive idx -> consecutive q within a row: 128B-coalesced wavefronts
#pragma unroll
        for (int k = 0; k < 3; k++) {
            int idx = tid + k * NTHREADS;
            if (idx < CH * YROWS * YCHUNK) {
                int c   = idx / (YROWS * YCHUNK);
                int rem = idx - c * (YROWS * YCHUNK);
                int r   = rem / YCHUNK;
                int q   = rem - r * YCHUNK;
                int gh  = h0 + r - PAD;
                int gw  = w0 - 4 + q * 4;
                bool ok = ((unsigned)gh < (unsigned)H_) &&
                          ((unsigned)gw <= (unsigned)(W_ - 4));
                const float* src = ok
                    ? yb + (size_t)(c0 + c) * HW_ + gh * W_ + gw
                    : yb;
                uint32_t dst = ys_base +
                    (uint32_t)(c * (YROWS * YPITCH) + r * YPITCH + q * 4) * 4u;
                cp16(dst, src, ok ? 16 : 0);
            }
        }
        cp_commit();
    };

    // accumulators: acc[j][q], pixel pair (2q, 2q+1); 18 u64 = 36 regs
    u64 acc[K_][2];
#pragma unroll
    for (int j = 0; j < K_; j++) { acc[j][0] = 0ull; acc[j][1] = 0ull; }

    prefetch(0, 0);

    for (int s = 0; s < NSTAGE; s++) {
        cp_wait<0>();              // stage-s group (issued a full stage ago) complete
        __syncthreads();           // (a) everyone's stage-s data visible
                                   // (b) all compute(s-1) done -> buf (s+1)&1 free
        if (s + 1 < NSTAGE) prefetch(s + 1, (s + 1) & 1);   // overlaps compute(s)

        const int buf = s & 1;
        const float* xp   = sm + buf * BUFSZ + hr * XPITCH + wg * PXT;
        const float* yrow = sm + buf * BUFSZ + XSZ + (hr + io) * YPITCH + wg * PXT;

#pragma unroll
        for (int c = 0; c < CH; c++) {
            float4 xa = *(const float4*)xp;
            u64 xe0 = pack2(xa.x, xa.y);   // adjacent lanes of float4 -> coalescible
            u64 xe1 = pack2(xa.z, xa.w);

            float4 y0 = *(const float4*)(yrow);
            float4 y1 = *(const float4*)(yrow + 4);
            float4 y2 = *(const float4*)(yrow + 8);
            float yv[12] = {y0.x, y0.y, y0.z, y0.w,
                            y1.x, y1.y, y1.z, y1.w,
                            y2.x, y2.y, y2.z, y2.w};

            // even-aligned y pairs (coalescible packs)
            u64 ye[6];
#pragma unroll
            for (int t = 0; t < 6; t++) ye[t] = pack2(yv[2 * t], yv[2 * t + 1]);
            // odd-aligned y pairs (genuine movs, 5)
            u64 yo[5];
#pragma unroll
            for (int t = 0; t < 5; t++) yo[t] = pack2(yv[2 * t + 1], yv[2 * t + 2]);

            // even j = 2*je: pair index q + je
#pragma unroll
            for (int je = 0; je < 5; je++) {
                acc[2 * je][0] = ffma2u(xe0, ye[je],     acc[2 * je][0]);
                acc[2 * je][1] = ffma2u(xe1, ye[je + 1], acc[2 * je][1]);
            }
            // odd j = 2*jo+1: odd pair index q + jo
#pragma unroll
            for (int jo = 0; jo < 4; jo++) {
                acc[2 * jo + 1][0] = ffma2u(xe0, yo[jo],     acc[2 * jo + 1][0]);
                acc[2 * jo + 1][1] = ffma2u(xe1, yo[jo + 1], acc[2 * jo + 1][1]);
            }

            xp   += TH * XPITCH;
            yrow += YROWS * YPITCH;
        }
    }

    // ---- epilogue: 9 float4 stores ----
    const float inv_c = 1.0f / (float)C_;
    const int hrow = h0 + hr;
#pragma unroll
    for (int j = 0; j < K_; j++) {
        int o = io * K_ + j;
        float* op = out + (((size_t)b * NOFF + o) * H_ + hrow) * W_ + w0 + wg * PXT;
        float2 v0 = unpack2(acc[j][0]);
        float2 v1 = unpack2(acc[j][1]);
        *(float4*)op = make_float4(v0.x * inv_c, v0.y * inv_c,
                                   v1.x * inv_c, v1.y * inv_c);
    }
}

extern "C" void kernel_launch(void* const* d_in, const int* in_sizes, int n_in,
                              void* d_out, int out_size) {
    const float* x = (const float*)d_in[0];
    const float* y = (const float*)d_in[1];
    float* out = (float*)d_out;

    static bool attr_set = false;
    if (!attr_set) {
        cudaFuncSetAttribute(corr_kernel,
                             cudaFuncAttributeMaxDynamicSharedMemorySize,
                             SMEM_BYTES);
        attr_set = true;
    }

    dim3 grid(W_ / TW, H_ / TH, B_);   // 12 x 24 x 4 = 1152 blocks
    corr_kernel<<<grid, NTHREADS, SMEM_BYTES>>>(x, y, out);
}